// round 14
// baseline (speedup 1.0000x reference)
#include <cuda_runtime.h>
#include <cuda_bf16.h>
#include <cstdint>
#include <math.h>

#define NT 4096
#define ND 1024
#define NE 8
#define NF 2048
#define N2F 4096

#if defined(__CUDA_ARCH_FEAT_SM103_ALL) || defined(__CUDA_ARCH_FEAT_SM100_ALL)
#define TC_OK 1
#else
#define TC_OK 0
#endif

// ---------------- scratch ----------------
__device__ int      g_cnt[NE];
__device__ int      g_tok[NE * NT];
__device__ float    g_wt[NT * 2];
__device__ int      g_slot[NT * 2];
__device__ int      g_eid[NT * 2];
__device__ uint32_t g_hidden_pk[(size_t)NE * NT * NF]; // bf16 hi|lo pack
__device__ float    g_y[(size_t)NE * NT * ND];

// ---------------- helpers ----------------
__device__ __forceinline__ uint32_t smem_u32(const void* p) {
    uint32_t a;
    asm("{ .reg .u64 t; cvta.to.shared.u64 t, %1; cvt.u32.u64 %0, t; }" : "=r"(a) : "l"(p));
    return a;
}
__device__ __forceinline__ uint32_t elect1() {
    uint32_t r;
    asm volatile("{ .reg .pred p; elect.sync _|p, 0xFFFFFFFF; selp.b32 %0,1,0,p; }" : "=r"(r));
    return r;
}
__device__ __forceinline__ uint32_t ctarank() {
    uint32_t r; asm("mov.u32 %0, %%cluster_ctarank;" : "=r"(r)); return r;
}
#define MBAR_INIT(a, c) asm volatile("mbarrier.init.shared.b64 [%0], %1;" :: "r"(a), "r"(c) : "memory")
#define MBAR_INVAL(a)   asm volatile("mbarrier.inval.shared.b64 [%0];" :: "r"(a) : "memory")
#define MBAR_WAIT_CL(a, ph) do { uint32_t _m=(a); uint32_t _p=(ph); uint32_t _d;                            \
    asm volatile("{ .reg .pred p; mbarrier.try_wait.parity.acquire.cluster.shared::cta.b64 p,[%1],%2; "    \
                 "selp.b32 %0,1,0,p; }" : "=r"(_d) : "r"(_m), "r"(_p) : "memory");                          \
    if (!_d) { asm volatile("{ .reg .pred P1; WL%=: "                                                      \
        "mbarrier.try_wait.parity.acquire.cluster.shared::cta.b64 P1,[%0],%1,0x989680; "                   \
        "@P1 bra.uni WD%=; bra.uni WL%=; WD%=: }" :: "r"(_m), "r"(_p) : "memory"); } } while (0)
#define FENCE_ASYNC_ALL() asm volatile("fence.proxy.async;" ::: "memory")
#define BAR_SYNC(id, n) asm volatile("bar.sync %0, %1;" :: "r"(id), "r"(n) : "memory")
#define CLUSTER_SYNC() do { \
    asm volatile("barrier.cluster.arrive.aligned;" ::: "memory"); \
    asm volatile("barrier.cluster.wait.aligned;" ::: "memory"); } while (0)
#define MBAR_ARRIVE_R0(local_a) do { uint32_t _r;                                        \
    asm("mapa.shared::cluster.u32 %0, %1, 0;" : "=r"(_r) : "r"(local_a));                \
    asm volatile("mbarrier.arrive.shared::cluster.b64 _, [%0];" :: "r"(_r) : "memory"); } while (0)

#define SWZ(x) ((x) ^ (((x) >> 3) & 0x70))

#if TC_OK
#define TCG_ALLOC2(sa, n)  asm volatile("tcgen05.alloc.cta_group::2.sync.aligned.shared::cta.b32 [%0], %1;" :: "r"(sa), "r"(n) : "memory")
#define TCG_DEALLOC2(t, n) asm volatile("tcgen05.dealloc.cta_group::2.sync.aligned.b32 %0, %1;" :: "r"(t), "r"(n))
#define TCG_RELINQ2()      asm volatile("tcgen05.relinquish_alloc_permit.cta_group::2.sync.aligned;")
#define TCG_COMMIT_MC(a, m) asm volatile( \
    "tcgen05.commit.cta_group::2.mbarrier::arrive::one.shared::cluster.multicast::cluster.b64 [%0], %1;" \
    :: "r"(a), "h"((uint16_t)(m)) : "memory")
#define TCG_FENCE_AFTER()  asm volatile("tcgen05.fence::after_thread_sync;" ::: "memory")
#define TCG_FENCE_BEFORE() asm volatile("tcgen05.fence::before_thread_sync;" ::: "memory")
#define TCG_WAIT_LD()      asm volatile("tcgen05.wait::ld.sync.aligned;" ::: "memory")
#define TCG_WAIT_ST()      asm volatile("tcgen05.wait::st.sync.aligned;" ::: "memory")

#define TCG_LD32(r, ta) \
    asm volatile("tcgen05.ld.sync.aligned.32x32b.x32.b32 " \
        "{%0,%1,%2,%3,%4,%5,%6,%7,%8,%9,%10,%11,%12,%13,%14,%15," \
        "%16,%17,%18,%19,%20,%21,%22,%23,%24,%25,%26,%27,%28,%29,%30,%31}, [%32];" \
        : "=r"((r)[0]),"=r"((r)[1]),"=r"((r)[2]),"=r"((r)[3]),"=r"((r)[4]),"=r"((r)[5]),"=r"((r)[6]),"=r"((r)[7]), \
          "=r"((r)[8]),"=r"((r)[9]),"=r"((r)[10]),"=r"((r)[11]),"=r"((r)[12]),"=r"((r)[13]),"=r"((r)[14]),"=r"((r)[15]), \
          "=r"((r)[16]),"=r"((r)[17]),"=r"((r)[18]),"=r"((r)[19]),"=r"((r)[20]),"=r"((r)[21]),"=r"((r)[22]),"=r"((r)[23]), \
          "=r"((r)[24]),"=r"((r)[25]),"=r"((r)[26]),"=r"((r)[27]),"=r"((r)[28]),"=r"((r)[29]),"=r"((r)[30]),"=r"((r)[31]) \
        : "r"(ta))

#define TCG_ST32_Z(ta) \
    asm volatile("tcgen05.st.sync.aligned.32x32b.x32.b32 [%0], " \
        "{%1,%1,%1,%1,%1,%1,%1,%1,%1,%1,%1,%1,%1,%1,%1,%1," \
        "%1,%1,%1,%1,%1,%1,%1,%1,%1,%1,%1,%1,%1,%1,%1,%1};" \
        :: "r"(ta), "r"(0u) : "memory")

__device__ __forceinline__ uint64_t descK(uint32_t a) {   // K-major SW128: LBO=1, SBO=64
    return ((uint64_t)2 << 61) | ((uint64_t)1 << 46) | ((uint64_t)64 << 32) |
           ((uint64_t)1 << 16) | ((a >> 4) & 0x3FFF);
}
// cg2 kind::f16 idesc: dtype=F32, a/btype=BF16, K-major, N=256, M=256
#define IDESC2 ((1u<<4) | (1u<<7) | (1u<<10) | (32u<<17) | (16u<<24))

__device__ __forceinline__ void mma2_n256(uint32_t d, uint64_t ad, uint64_t bd) {
    asm volatile("{ .reg .pred p; setp.ne.u32 p, %4, 0;\n\t"
        "tcgen05.mma.cta_group::2.kind::f16 [%0], %1, %2, %3, {%5,%5,%5,%5,%5,%5,%5,%5}, p; }"
        :: "r"(d), "l"(ad), "l"(bd), "r"(IDESC2), "r"(1u), "r"(0u) : "memory");
}
#endif // TC_OK

__device__ __forceinline__ uint32_t bf2(float h, float l) {
    uint32_t r; asm("cvt.rn.bf16x2.f32 %0, %1, %2;" : "=r"(r) : "f"(h), "f"(l)); return r;
}
__device__ __forceinline__ void split8(float4 v0, float4 v1, uint4& hi, uint4& lo) {
    uint32_t u0 = __float_as_uint(v0.x), u1 = __float_as_uint(v0.y);
    uint32_t u2 = __float_as_uint(v0.z), u3 = __float_as_uint(v0.w);
    uint32_t u4 = __float_as_uint(v1.x), u5 = __float_as_uint(v1.y);
    uint32_t u6 = __float_as_uint(v1.z), u7 = __float_as_uint(v1.w);
    hi.x = __byte_perm(u0, u1, 0x7632); hi.y = __byte_perm(u2, u3, 0x7632);
    hi.z = __byte_perm(u4, u5, 0x7632); hi.w = __byte_perm(u6, u7, 0x7632);
    float l0 = v0.x - __uint_as_float(u0 & 0xffff0000u);
    float l1 = v0.y - __uint_as_float(u1 & 0xffff0000u);
    float l2 = v0.z - __uint_as_float(u2 & 0xffff0000u);
    float l3 = v0.w - __uint_as_float(u3 & 0xffff0000u);
    float l4 = v1.x - __uint_as_float(u4 & 0xffff0000u);
    float l5 = v1.y - __uint_as_float(u5 & 0xffff0000u);
    float l6 = v1.z - __uint_as_float(u6 & 0xffff0000u);
    float l7 = v1.w - __uint_as_float(u7 & 0xffff0000u);
    lo.x = bf2(l1, l0); lo.y = bf2(l3, l2); lo.z = bf2(l5, l4); lo.w = bf2(l7, l6);
}

// SMEM per CTA: stage b @ data0 + b*98304:
//   A set s @ +s*32768 (hi @+0, lo @+16384); B @ +65536 (hi), +81920 (lo)
// hdr: done[pp][b] @ 8+pp*16+b*8 (commit mc); ready[pp] @ 40+pp*8 (count 2, rank0)
#define ST_SIZE  98304
#define OFF_B    65536
#define DYNSMEM  (2 * ST_SIZE + 2048)

// ======================= zero counters =======================
__global__ void zero_cnt_kernel() {
    if (threadIdx.x < NE) g_cnt[threadIdx.x] = 0;
}

// ======================= router =======================
__global__ void router_kernel(const float* __restrict__ x,
                              const float* __restrict__ Wr,
                              const float* __restrict__ temp) {
    int t    = (blockIdx.x * blockDim.x + threadIdx.x) >> 5;
    int lane = threadIdx.x & 31;
    if (t >= NT) return;
    const float4* xr = (const float4*)(x + (size_t)t * ND);
    const float4* wr4 = (const float4*)Wr;
    float acc[NE];
#pragma unroll
    for (int e = 0; e < NE; e++) acc[e] = 0.f;
    for (int d4 = lane; d4 < ND / 4; d4 += 32) {
        float4 xv = xr[d4];
        float xs[4] = {xv.x, xv.y, xv.z, xv.w};
#pragma unroll
        for (int j = 0; j < 4; j++) {
            int d = 4 * d4 + j;
            float4 w0 = wr4[d * 2], w1 = wr4[d * 2 + 1];
            acc[0] = fmaf(xs[j], w0.x, acc[0]);
            acc[1] = fmaf(xs[j], w0.y, acc[1]);
            acc[2] = fmaf(xs[j], w0.z, acc[2]);
            acc[3] = fmaf(xs[j], w0.w, acc[3]);
            acc[4] = fmaf(xs[j], w1.x, acc[4]);
            acc[5] = fmaf(xs[j], w1.y, acc[5]);
            acc[6] = fmaf(xs[j], w1.z, acc[6]);
            acc[7] = fmaf(xs[j], w1.w, acc[7]);
        }
    }
#pragma unroll
    for (int e = 0; e < NE; e++) {
#pragma unroll
        for (int off = 16; off > 0; off >>= 1)
            acc[e] += __shfl_xor_sync(0xffffffffu, acc[e], off);
    }
    if (lane == 0) {
        float ti = 1.0f / temp[0];
#pragma unroll
        for (int e = 0; e < NE; e++) acc[e] *= ti;
        int i0 = 0; float l0 = acc[0];
#pragma unroll
        for (int e = 1; e < NE; e++) if (acc[e] > l0) { l0 = acc[e]; i0 = e; }
        int i1 = -1; float l1 = -3.4e38f;
#pragma unroll
        for (int e = 0; e < NE; e++)
            if (e != i0 && acc[e] > l1) { l1 = acc[e]; i1 = e; }
        float ex  = expf(l1 - l0);
        float w1v = ex / (1.f + ex);
        float w0v = 1.f - w1v;
        int p0 = atomicAdd(&g_cnt[i0], 1);
        int p1 = atomicAdd(&g_cnt[i1], 1);
        g_tok[i0 * NT + p0] = t;
        g_tok[i1 * NT + p1] = t;
        g_slot[2 * t]     = i0 * NT + p0;
        g_slot[2 * t + 1] = i1 * NT + p1;
        g_wt[2 * t]     = w0v;
        g_wt[2 * t + 1] = w1v;
        g_eid[2 * t]     = i0;
        g_eid[2 * t + 1] = i1;
    }
}

// ======================= cg2 GEMM1 + SwiGLU (double-buffered stages) =======================
__global__ __launch_bounds__(256, 1) __cluster_dims__(2, 1, 1)
void gemm1_tc(const float* __restrict__ x,
              const float* __restrict__ W1,
              const float* __restrict__ b1) {
#if TC_OK
    int e    = blockIdx.z;
    int cnt  = g_cnt[e];
    int row0 = (blockIdx.x >> 1) * 512;
    if (row0 >= cnt) return;
    int na0 = blockIdx.y * 128;
    uint32_t rank = ctarank();

    extern __shared__ char dynsmem[];
    uint32_t raw   = smem_u32(dynsmem);
    uint32_t base  = (raw + 1023) & ~1023u;
    uint32_t hdr   = base;
    uint32_t data0 = base + 1024;
    char* pdata = dynsmem + (data0 - raw);

    int tid = threadIdx.x, wid = tid >> 5, lane = tid & 31;
    int pp = wid >> 2;
    int ptid = tid & 127;

    if (tid == 0) {
        MBAR_INIT(hdr + 8, 1);  MBAR_INIT(hdr + 16, 1);   // done pipe0: stage0, stage1
        MBAR_INIT(hdr + 24, 1); MBAR_INIT(hdr + 32, 1);   // done pipe1
        MBAR_INIT(hdr + 40, 2); MBAR_INIT(hdr + 48, 2);   // ready (rank0)
    }
    if (wid == 0) { TCG_ALLOC2(hdr, 512); TCG_RELINQ2(); }
    __syncthreads();
    uint32_t tmem;
    asm("ld.shared.b32 %0, [%1];" : "=r"(tmem) : "r"(hdr));

    {
        uint32_t zb = tmem + ((uint32_t)(wid & 3) << 21) + (uint32_t)(pp * 256);
#pragma unroll
        for (int j = 0; j < 8; j++) TCG_ST32_Z(zb + j * 32);
        TCG_WAIT_ST();
    }
    TCG_FENCE_BEFORE();
    __syncthreads();
    CLUSTER_SYNC();
    TCG_FENCE_AFTER();

    const float* ap[2];
#pragma unroll
    for (int s = 0; s < 2; s++) {
        int rr = row0 + s * 256 + (int)rank * 128 + ptid;
        if (rr >= cnt) rr = cnt - 1;
        ap[s] = x + (size_t)g_tok[e * NT + rr] * ND + pp * 32;
    }
    const float* bcol = W1 + (size_t)e * ND * N2F +
        ((rank == 0) ? (size_t)(na0 + ptid) : ((size_t)NF + na0 + ptid));

    uint32_t mbR = hdr + 40 + 8 * pp;

    const int CH = ND / 64; // 16
    for (int c = 0; c < CH; c++) {
        int b = c & 1;
        int k0 = c * 64;
        uint32_t st = data0 + b * ST_SIZE;
        char* sp = pdata + b * ST_SIZE;
        uint32_t mbD = hdr + 8 + pp * 16 + b * 8;
        float4 av[2][8];
#pragma unroll
        for (int s = 0; s < 2; s++) {
            const float4* p = (const float4*)(ap[s] + k0);
#pragma unroll
            for (int j = 0; j < 8; j++) av[s][j] = p[j];
        }
        float bv[32];
        {
            const float* gc = bcol + (size_t)(k0 + pp * 32) * N2F;
#pragma unroll
            for (int j = 0; j < 32; j++) bv[j] = gc[(size_t)j * N2F];
        }
        // stage b free for our k-half once our commit(c-2) fired
        if (c >= 2) MBAR_WAIT_CL(mbD, ((c - 2) >> 1) & 1);
#pragma unroll
        for (int s = 0; s < 2; s++) {
            char* sa = sp + s * 32768;
#pragma unroll
            for (int i = 0; i < 4; i++) {
                uint4 hi, lo; split8(av[s][2 * i], av[s][2 * i + 1], hi, lo);
                uint32_t off = SWZ((uint32_t)(ptid * 128 + pp * 64 + i * 16));
                *(uint4*)(sa + off)         = hi;
                *(uint4*)(sa + 16384 + off) = lo;
            }
        }
        {
            char* sb = sp + OFF_B;
#pragma unroll
            for (int kb = 0; kb < 4; kb++) {
                float4 v0 = {bv[8*kb], bv[8*kb+1], bv[8*kb+2], bv[8*kb+3]};
                float4 v1 = {bv[8*kb+4], bv[8*kb+5], bv[8*kb+6], bv[8*kb+7]};
                uint4 hi, lo; split8(v0, v1, hi, lo);
                uint32_t off = SWZ((uint32_t)(ptid * 128 + pp * 64 + kb * 16));
                *(uint4*)(sb + off)         = hi;
                *(uint4*)(sb + 16384 + off) = lo;
            }
        }
        FENCE_ASYNC_ALL();
        BAR_SYNC(1 + pp, 128);
        if ((wid & 3) == 0 && elect1()) {
            MBAR_ARRIVE_R0(mbR);
            if (rank == 0) {
                MBAR_WAIT_CL(mbR, c & 1);
                uint64_t dA0 = descK(st);
                uint64_t dB0 = descK(st + OFF_B);
#pragma unroll
                for (int pi = 0; pi < 3; pi++) {
                    uint64_t aBase = dA0 + (uint64_t)((pi == 2) ? 1024 : 0);
                    uint64_t bBase = dB0 + (uint64_t)((pi == 1) ? 1024 : 0);
#pragma unroll
                    for (int ksl = 0; ksl < 2; ksl++) {
                        int ks = 2 * pp + ksl;
#pragma unroll
                        for (int s = 0; s < 2; s++) {
                            uint64_t ad = aBase + (uint64_t)(s * 2048 + ks * 2);
                            uint64_t bd = bBase + (uint64_t)(ks * 2);
                            mma2_n256(tmem + s * 256, ad, bd);
                        }
                    }
                }
                TCG_COMMIT_MC(mbD, 0x3);
            }
        }
    }
    __syncthreads();
    // drain: each pipe's last commit per stage: chunk CH-2 (stage 0), CH-1 (stage 1)
#pragma unroll
    for (int p2 = 0; p2 < 2; p2++)
#pragma unroll
        for (int b2 = 0; b2 < 2; b2++)
            MBAR_WAIT_CL(hdr + 8 + p2 * 16 + b2 * 8, ((CH - 2 + b2) >> 1) & 1);
    TCG_FENCE_AFTER();
    int tl = wid >> 2;
    int row = row0 + tl * 256 + (int)rank * 128 + (wid & 3) * 32 + lane;
    bool act = row < cnt;
    const float* b1a = b1 + (size_t)e * N2F + na0;
    const float* b1g = b1 + (size_t)e * N2F + NF + na0;
    for (int j = 0; j < 4; j++) {
        uint32_t ar[32], gr[32];
        TCG_LD32(ar, tmem + tl * 256 + j * 32);
        TCG_LD32(gr, tmem + tl * 256 + 128 + j * 32);
        TCG_WAIT_LD();
        if (act) {
            uint32_t pk[32];
#pragma unroll
            for (int q = 0; q < 32; q++) {
                float avv = __uint_as_float(ar[q]) + b1a[j * 32 + q];
                float gvv = __uint_as_float(gr[q]) + b1g[j * 32 + q];
                float hv = avv * (gvv / (1.f + __expf(-gvv)));
                uint32_t u = __float_as_uint(hv);
                float lof = hv - __uint_as_float(u & 0xffff0000u);
                uint16_t lob = __bfloat16_as_ushort(__float2bfloat16(lof));
                pk[q] = (u >> 16) | ((uint32_t)lob << 16);
            }
            uint32_t* dst = g_hidden_pk + ((size_t)e * NT + row) * NF + na0 + j * 32;
#pragma unroll
            for (int q = 0; q < 8; q++) *(uint4*)(dst + 4 * q) = *(uint4*)&pk[4 * q];
        }
    }
    TCG_FENCE_BEFORE();
    __syncthreads();
    if (tid == 0) {
        MBAR_INVAL(hdr + 8);  MBAR_INVAL(hdr + 16);
        MBAR_INVAL(hdr + 24); MBAR_INVAL(hdr + 32);
        MBAR_INVAL(hdr + 40); MBAR_INVAL(hdr + 48);
    }
    CLUSTER_SYNC();
    if (wid == 0) { TCG_DEALLOC2(tmem, 512); }
#endif
}

// ======================= cg2 GEMM2 (double-buffered stages) =======================
__global__ __launch_bounds__(256, 1) __cluster_dims__(2, 1, 1)
void gemm2_tc(const float* __restrict__ W2) {
#if TC_OK
    int e    = blockIdx.z;
    int cnt  = g_cnt[e];
    int row0 = (blockIdx.x >> 1) * 512;
    if (row0 >= cnt) return;
    int n0 = blockIdx.y * 256;
    uint32_t rank = ctarank();

    extern __shared__ char dynsmem[];
    uint32_t raw   = smem_u32(dynsmem);
    uint32_t base  = (raw + 1023) & ~1023u;
    uint32_t hdr   = base;
    uint32_t data0 = base + 1024;
    char* pdata = dynsmem + (data0 - raw);

    int tid = threadIdx.x, wid = tid >> 5, lane = tid & 31;
    int pp = wid >> 2;
    int ptid = tid & 127;

    if (tid == 0) {
        MBAR_INIT(hdr + 8, 1);  MBAR_INIT(hdr + 16, 1);
        MBAR_INIT(hdr + 24, 1); MBAR_INIT(hdr + 32, 1);
        MBAR_INIT(hdr + 40, 2); MBAR_INIT(hdr + 48, 2);
    }
    if (wid == 0) { TCG_ALLOC2(hdr, 512); TCG_RELINQ2(); }
    __syncthreads();
    uint32_t tmem;
    asm("ld.shared.b32 %0, [%1];" : "=r"(tmem) : "r"(hdr));

    {
        uint32_t zb = tmem + ((uint32_t)(wid & 3) << 21) + (uint32_t)(pp * 256);
#pragma unroll
        for (int j = 0; j < 8; j++) TCG_ST32_Z(zb + j * 32);
        TCG_WAIT_ST();
    }
    TCG_FENCE_BEFORE();
    __syncthreads();
    CLUSTER_SYNC();
    TCG_FENCE_AFTER();

    const uint32_t* hp[2];
#pragma unroll
    for (int s = 0; s < 2; s++) {
        int rr = row0 + s * 256 + (int)rank * 128 + ptid;
        if (rr >= cnt) rr = cnt - 1;
        hp[s] = g_hidden_pk + ((size_t)e * NT + rr) * NF + pp * 32;
    }
    const float* bcol = W2 + (size_t)e * NF * ND + n0 + (int)rank * 128 + ptid;

    uint32_t mbR = hdr + 40 + 8 * pp;

    const int CH = NF / 64; // 32
    for (int c = 0; c < CH; c++) {
        int b = c & 1;
        int k0 = c * 64;
        uint32_t st = data0 + b * ST_SIZE;
        char* sp = pdata + b * ST_SIZE;
        uint32_t mbD = hdr + 8 + pp * 16 + b * 8;
        uint4 aw[2][8];
#pragma unroll
        for (int s = 0; s < 2; s++) {
            const uint4* p = (const uint4*)(hp[s] + k0);
#pragma unroll
            for (int j = 0; j < 8; j++) aw[s][j] = p[j];
        }
        float bv[32];
        {
            const float* gc = bcol + (size_t)(k0 + pp * 32) * ND;
#pragma unroll
            for (int j = 0; j < 32; j++) bv[j] = gc[(size_t)j * ND];
        }
        if (c >= 2) MBAR_WAIT_CL(mbD, ((c - 2) >> 1) & 1);
#pragma unroll
        for (int s = 0; s < 2; s++) {
            char* sa = sp + s * 32768;
#pragma unroll
            for (int i = 0; i < 4; i++) {
                uint4 w0 = aw[s][2 * i], w1 = aw[s][2 * i + 1];
                uint4 hi, lo;
                hi.x = __byte_perm(w0.x, w0.y, 0x5410); lo.x = __byte_perm(w0.x, w0.y, 0x7632);
                hi.y = __byte_perm(w0.z, w0.w, 0x5410); lo.y = __byte_perm(w0.z, w0.w, 0x7632);
                hi.z = __byte_perm(w1.x, w1.y, 0x5410); lo.z = __byte_perm(w1.x, w1.y, 0x7632);
                hi.w = __byte_perm(w1.z, w1.w, 0x5410); lo.w = __byte_perm(w1.z, w1.w, 0x7632);
                uint32_t off = SWZ((uint32_t)(ptid * 128 + pp * 64 + i * 16));
                *(uint4*)(sa + off)         = hi;
                *(uint4*)(sa + 16384 + off) = lo;
            }
        }
        {
            char* sb = sp + OFF_B;
#pragma unroll
            for (int kb = 0; kb < 4; kb++) {
                float4 v0 = {bv[8*kb], bv[8*kb+1], bv[8*kb+2], bv[8*kb+3]};
                float4 v1 = {bv[8*kb+4], bv[8*kb+5], bv[8*kb+6], bv[8*kb+7]};
                uint4 hi, lo; split8(v0, v1, hi, lo);
                uint32_t off = SWZ((uint32_t)(ptid * 128 + pp * 64 + kb * 16));
                *(uint4*)(sb + off)         = hi;
                *(uint4*)(sb + 16384 + off) = lo;
            }
        }
        FENCE_ASYNC_ALL();
        BAR_SYNC(1 + pp, 128);
        if ((wid & 3) == 0 && elect1()) {
            MBAR_ARRIVE_R0(mbR);
            if (rank == 0) {
                MBAR_WAIT_CL(mbR, c & 1);
                uint64_t dA0 = descK(st);
                uint64_t dB0 = descK(st + OFF_B);
#pragma unroll
                for (int pi = 0; pi < 3; pi++) {
                    uint64_t aBase = dA0 + (uint64_t)((pi == 2) ? 1024 : 0);
                    uint64_t bBase = dB0 + (uint64_t)((pi == 1) ? 1024 : 0);
#pragma unroll
                    for (int ksl = 0; ksl < 2; ksl++) {
                        int ks = 2 * pp + ksl;
#pragma unroll
                        for (int s = 0; s < 2; s++) {
                            uint64_t ad = aBase + (uint64_t)(s * 2048 + ks * 2);
                            uint64_t bd = bBase + (uint64_t)(ks * 2);
                            mma2_n256(tmem + s * 256, ad, bd);
                        }
                    }
                }
                TCG_COMMIT_MC(mbD, 0x3);
            }
        }
    }
    __syncthreads();
#pragma unroll
    for (int p2 = 0; p2 < 2; p2++)
#pragma unroll
        for (int b2 = 0; b2 < 2; b2++)
            MBAR_WAIT_CL(hdr + 8 + p2 * 16 + b2 * 8, ((CH - 2 + b2) >> 1) & 1);
    TCG_FENCE_AFTER();
    int tl = wid >> 2;
    int row = row0 + tl * 256 + (int)rank * 128 + (wid & 3) * 32 + lane;
    bool act = row < cnt;
    for (int j = 0; j < 8; j++) {
        uint32_t yr[32];
        TCG_LD32(yr, tmem + tl * 256 + j * 32);
        TCG_WAIT_LD();
        if (act) {
            float* dst = g_y + ((size_t)e * NT + row) * ND + n0 + j * 32;
#pragma unroll
            for (int q = 0; q < 8; q++) *(uint4*)(dst + 4 * q) = *(uint4*)&yr[4 * q];
        }
    }
    TCG_FENCE_BEFORE();
    __syncthreads();
    if (tid == 0) {
        MBAR_INVAL(hdr + 8);  MBAR_INVAL(hdr + 16);
        MBAR_INVAL(hdr + 24); MBAR_INVAL(hdr + 32);
        MBAR_INVAL(hdr + 40); MBAR_INVAL(hdr + 48);
    }
    CLUSTER_SYNC();
    if (wid == 0) { TCG_DEALLOC2(tmem, 512); }
#endif
}

// ======================= combine =======================
__global__ void combine_kernel(const float* __restrict__ b2, float* __restrict__ out) {
    int t = blockIdx.x;
    float w0 = g_wt[2 * t], w1 = g_wt[2 * t + 1];
    int s0 = g_slot[2 * t], s1 = g_slot[2 * t + 1];
    int e0 = g_eid[2 * t],  e1 = g_eid[2 * t + 1];
    int c = threadIdx.x * 4;
    float4 y0  = *(const float4*)(g_y + (size_t)s0 * ND + c);
    float4 y1  = *(const float4*)(g_y + (size_t)s1 * ND + c);
    float4 bb0 = *(const float4*)(b2 + (size_t)e0 * ND + c);
    float4 bb1 = *(const float4*)(b2 + (size_t)e1 * ND + c);
    float4 o;
    o.x = w0 * (y0.x + bb0.x) + w1 * (y1.x + bb1.x);
    o.y = w0 * (y0.y + bb0.y) + w1 * (y1.y + bb1.y);
    o.z = w0 * (y0.z + bb0.z) + w1 * (y1.z + bb1.z);
    o.w = w0 * (y0.w + bb0.w) + w1 * (y1.w + bb1.w);
    *(float4*)(out + (size_t)t * ND + c) = o;
}

// ======================= launch =======================
extern "C" void kernel_launch(void* const* d_in, const int* in_sizes, int n_in,
                              void* d_out, int out_size) {
    const float* x    = (const float*)d_in[0];
    const float* Wr   = (const float*)d_in[1];
    const float* temp = (const float*)d_in[2];
    const float* W1   = (const float*)d_in[3];
    const float* b1   = (const float*)d_in[4];
    const float* W2   = (const float*)d_in[5];
    const float* b2   = (const float*)d_in[6];
    float* out = (float*)d_out;

    cudaFuncSetAttribute(gemm1_tc, cudaFuncAttributeMaxDynamicSharedMemorySize, DYNSMEM);
    cudaFuncSetAttribute(gemm2_tc, cudaFuncAttributeMaxDynamicSharedMemorySize, DYNSMEM);

    zero_cnt_kernel<<<1, 32>>>();
    router_kernel<<<NT / 8, 256>>>(x, Wr, temp);
    gemm1_tc<<<dim3((NT / 512) * 2, NF / 128, NE), 256, DYNSMEM>>>(x, W1, b1);
    gemm2_tc<<<dim3((NT / 512) * 2, ND / 256, NE), 256, DYNSMEM>>>(W2);
    combine_kernel<<<NT, 256>>>(b2, out);
}

// round 15
// speedup vs baseline: 1.1212x; 1.1212x over previous
#include <cuda_runtime.h>
#include <cuda_bf16.h>
#include <cstdint>
#include <math.h>

#define NT 4096
#define ND 1024
#define NE 8
#define NF 2048
#define N2F 4096

#if defined(__CUDA_ARCH_FEAT_SM103_ALL) || defined(__CUDA_ARCH_FEAT_SM100_ALL)
#define TC_OK 1
#else
#define TC_OK 0
#endif

// ---------------- scratch ----------------
__device__ int      g_cnt[NE];
__device__ int      g_tok[NE * NT];
__device__ float    g_wt[NT * 2];
__device__ int      g_slot[NT * 2];
__device__ int      g_eid[NT * 2];
__device__ uint32_t g_hidden_pk[(size_t)NE * NT * NF]; // bf16 hi|lo pack
__device__ float    g_y[(size_t)NE * NT * ND];

// ---------------- helpers ----------------
__device__ __forceinline__ uint32_t smem_u32(const void* p) {
    uint32_t a;
    asm("{ .reg .u64 t; cvta.to.shared.u64 t, %1; cvt.u32.u64 %0, t; }" : "=r"(a) : "l"(p));
    return a;
}
__device__ __forceinline__ uint32_t elect1() {
    uint32_t r;
    asm volatile("{ .reg .pred p; elect.sync _|p, 0xFFFFFFFF; selp.b32 %0,1,0,p; }" : "=r"(r));
    return r;
}
__device__ __forceinline__ uint32_t ctarank() {
    uint32_t r; asm("mov.u32 %0, %%cluster_ctarank;" : "=r"(r)); return r;
}
#define MBAR_INIT(a, c) asm volatile("mbarrier.init.shared.b64 [%0], %1;" :: "r"(a), "r"(c) : "memory")
#define MBAR_INVAL(a)   asm volatile("mbarrier.inval.shared.b64 [%0];" :: "r"(a) : "memory")
#define MBAR_WAIT_CL(a, ph) do { uint32_t _m=(a); uint32_t _p=(ph); uint32_t _d;                            \
    asm volatile("{ .reg .pred p; mbarrier.try_wait.parity.acquire.cluster.shared::cta.b64 p,[%1],%2; "    \
                 "selp.b32 %0,1,0,p; }" : "=r"(_d) : "r"(_m), "r"(_p) : "memory");                          \
    if (!_d) { asm volatile("{ .reg .pred P1; WL%=: "                                                      \
        "mbarrier.try_wait.parity.acquire.cluster.shared::cta.b64 P1,[%0],%1,0x989680; "                   \
        "@P1 bra.uni WD%=; bra.uni WL%=; WD%=: }" :: "r"(_m), "r"(_p) : "memory"); } } while (0)
// cta-scope async-proxy fence (CUTLASS cg2 producer pattern; avoids cluster-scope
// fence lowering that can emit CCTL.IVALL per chunk). Cross-CTA ordering comes
// from the release-arrive + acquire-wait pair on rank0's mbarrier.
#define FENCE_ASYNC() asm volatile("fence.proxy.async.shared::cta;" ::: "memory")
#define BAR_SYNC(id, n) asm volatile("bar.sync %0, %1;" :: "r"(id), "r"(n) : "memory")
#define CLUSTER_SYNC() do { \
    asm volatile("barrier.cluster.arrive.aligned;" ::: "memory"); \
    asm volatile("barrier.cluster.wait.aligned;" ::: "memory"); } while (0)
#define MBAR_ARRIVE_R0(local_a) do { uint32_t _r;                                        \
    asm("mapa.shared::cluster.u32 %0, %1, 0;" : "=r"(_r) : "r"(local_a));                \
    asm volatile("mbarrier.arrive.shared::cluster.b64 _, [%0];" :: "r"(_r) : "memory"); } while (0)

#define SWZ(x) ((x) ^ (((x) >> 3) & 0x70))

#if TC_OK
#define TCG_ALLOC2(sa, n)  asm volatile("tcgen05.alloc.cta_group::2.sync.aligned.shared::cta.b32 [%0], %1;" :: "r"(sa), "r"(n) : "memory")
#define TCG_DEALLOC2(t, n) asm volatile("tcgen05.dealloc.cta_group::2.sync.aligned.b32 %0, %1;" :: "r"(t), "r"(n))
#define TCG_RELINQ2()      asm volatile("tcgen05.relinquish_alloc_permit.cta_group::2.sync.aligned;")
#define TCG_COMMIT_MC(a, m) asm volatile( \
    "tcgen05.commit.cta_group::2.mbarrier::arrive::one.shared::cluster.multicast::cluster.b64 [%0], %1;" \
    :: "r"(a), "h"((uint16_t)(m)) : "memory")
#define TCG_FENCE_AFTER()  asm volatile("tcgen05.fence::after_thread_sync;" ::: "memory")
#define TCG_FENCE_BEFORE() asm volatile("tcgen05.fence::before_thread_sync;" ::: "memory")
#define TCG_WAIT_LD()      asm volatile("tcgen05.wait::ld.sync.aligned;" ::: "memory")
#define TCG_WAIT_ST()      asm volatile("tcgen05.wait::st.sync.aligned;" ::: "memory")

#define TCG_LD32(r, ta) \
    asm volatile("tcgen05.ld.sync.aligned.32x32b.x32.b32 " \
        "{%0,%1,%2,%3,%4,%5,%6,%7,%8,%9,%10,%11,%12,%13,%14,%15," \
        "%16,%17,%18,%19,%20,%21,%22,%23,%24,%25,%26,%27,%28,%29,%30,%31}, [%32];" \
        : "=r"((r)[0]),"=r"((r)[1]),"=r"((r)[2]),"=r"((r)[3]),"=r"((r)[4]),"=r"((r)[5]),"=r"((r)[6]),"=r"((r)[7]), \
          "=r"((r)[8]),"=r"((r)[9]),"=r"((r)[10]),"=r"((r)[11]),"=r"((r)[12]),"=r"((r)[13]),"=r"((r)[14]),"=r"((r)[15]), \
          "=r"((r)[16]),"=r"((r)[17]),"=r"((r)[18]),"=r"((r)[19]),"=r"((r)[20]),"=r"((r)[21]),"=r"((r)[22]),"=r"((r)[23]), \
          "=r"((r)[24]),"=r"((r)[25]),"=r"((r)[26]),"=r"((r)[27]),"=r"((r)[28]),"=r"((r)[29]),"=r"((r)[30]),"=r"((r)[31]) \
        : "r"(ta))

#define TCG_ST32_Z(ta) \
    asm volatile("tcgen05.st.sync.aligned.32x32b.x32.b32 [%0], " \
        "{%1,%1,%1,%1,%1,%1,%1,%1,%1,%1,%1,%1,%1,%1,%1,%1," \
        "%1,%1,%1,%1,%1,%1,%1,%1,%1,%1,%1,%1,%1,%1,%1,%1};" \
        :: "r"(ta), "r"(0u) : "memory")

__device__ __forceinline__ uint64_t descK(uint32_t a) {   // K-major SW128: LBO=1, SBO=64
    return ((uint64_t)2 << 61) | ((uint64_t)1 << 46) | ((uint64_t)64 << 32) |
           ((uint64_t)1 << 16) | ((a >> 4) & 0x3FFF);
}
// cg2 kind::f16 idesc: dtype=F32, a/btype=BF16, K-major, N=256, M=256
#define IDESC2 ((1u<<4) | (1u<<7) | (1u<<10) | (32u<<17) | (16u<<24))

__device__ __forceinline__ void mma2_n256(uint32_t d, uint64_t ad, uint64_t bd) {
    asm volatile("{ .reg .pred p; setp.ne.u32 p, %4, 0;\n\t"
        "tcgen05.mma.cta_group::2.kind::f16 [%0], %1, %2, %3, {%5,%5,%5,%5,%5,%5,%5,%5}, p; }"
        :: "r"(d), "l"(ad), "l"(bd), "r"(IDESC2), "r"(1u), "r"(0u) : "memory");
}
#endif // TC_OK

__device__ __forceinline__ uint32_t bf2(float h, float l) {
    uint32_t r; asm("cvt.rn.bf16x2.f32 %0, %1, %2;" : "=r"(r) : "f"(h), "f"(l)); return r;
}
__device__ __forceinline__ void split8(float4 v0, float4 v1, uint4& hi, uint4& lo) {
    uint32_t u0 = __float_as_uint(v0.x), u1 = __float_as_uint(v0.y);
    uint32_t u2 = __float_as_uint(v0.z), u3 = __float_as_uint(v0.w);
    uint32_t u4 = __float_as_uint(v1.x), u5 = __float_as_uint(v1.y);
    uint32_t u6 = __float_as_uint(v1.z), u7 = __float_as_uint(v1.w);
    hi.x = __byte_perm(u0, u1, 0x7632); hi.y = __byte_perm(u2, u3, 0x7632);
    hi.z = __byte_perm(u4, u5, 0x7632); hi.w = __byte_perm(u6, u7, 0x7632);
    float l0 = v0.x - __uint_as_float(u0 & 0xffff0000u);
    float l1 = v0.y - __uint_as_float(u1 & 0xffff0000u);
    float l2 = v0.z - __uint_as_float(u2 & 0xffff0000u);
    float l3 = v0.w - __uint_as_float(u3 & 0xffff0000u);
    float l4 = v1.x - __uint_as_float(u4 & 0xffff0000u);
    float l5 = v1.y - __uint_as_float(u5 & 0xffff0000u);
    float l6 = v1.z - __uint_as_float(u6 & 0xffff0000u);
    float l7 = v1.w - __uint_as_float(u7 & 0xffff0000u);
    lo.x = bf2(l1, l0); lo.y = bf2(l3, l2); lo.z = bf2(l5, l4); lo.w = bf2(l7, l6);
}

// SMEM per CTA (after 1024-aligned data0):
//   A: set s (0,1) @ s*32768; plane hi @+0, lo @+16384   (64 KB: CTA's 128 rows per set)
//   B: hi @ 65536, lo @ 81920                            (32 KB: CTA's 128-col half)
// hdr: D0 @+8, D1 @+16 (commit multicast), R0 @+24, R1 @+32 (ready, count 2, rank0)
#define OFF_B    65536
#define DYNSMEM  100352

// ======================= zero counters =======================
__global__ void zero_cnt_kernel() {
    if (threadIdx.x < NE) g_cnt[threadIdx.x] = 0;
}

// ======================= router =======================
__global__ void router_kernel(const float* __restrict__ x,
                              const float* __restrict__ Wr,
                              const float* __restrict__ temp) {
    int t    = (blockIdx.x * blockDim.x + threadIdx.x) >> 5;
    int lane = threadIdx.x & 31;
    if (t >= NT) return;
    const float4* xr = (const float4*)(x + (size_t)t * ND);
    const float4* wr4 = (const float4*)Wr;
    float acc[NE];
#pragma unroll
    for (int e = 0; e < NE; e++) acc[e] = 0.f;
    for (int d4 = lane; d4 < ND / 4; d4 += 32) {
        float4 xv = xr[d4];
        float xs[4] = {xv.x, xv.y, xv.z, xv.w};
#pragma unroll
        for (int j = 0; j < 4; j++) {
            int d = 4 * d4 + j;
            float4 w0 = wr4[d * 2], w1 = wr4[d * 2 + 1];
            acc[0] = fmaf(xs[j], w0.x, acc[0]);
            acc[1] = fmaf(xs[j], w0.y, acc[1]);
            acc[2] = fmaf(xs[j], w0.z, acc[2]);
            acc[3] = fmaf(xs[j], w0.w, acc[3]);
            acc[4] = fmaf(xs[j], w1.x, acc[4]);
            acc[5] = fmaf(xs[j], w1.y, acc[5]);
            acc[6] = fmaf(xs[j], w1.z, acc[6]);
            acc[7] = fmaf(xs[j], w1.w, acc[7]);
        }
    }
#pragma unroll
    for (int e = 0; e < NE; e++) {
#pragma unroll
        for (int off = 16; off > 0; off >>= 1)
            acc[e] += __shfl_xor_sync(0xffffffffu, acc[e], off);
    }
    if (lane == 0) {
        float ti = 1.0f / temp[0];
#pragma unroll
        for (int e = 0; e < NE; e++) acc[e] *= ti;
        int i0 = 0; float l0 = acc[0];
#pragma unroll
        for (int e = 1; e < NE; e++) if (acc[e] > l0) { l0 = acc[e]; i0 = e; }
        int i1 = -1; float l1 = -3.4e38f;
#pragma unroll
        for (int e = 0; e < NE; e++)
            if (e != i0 && acc[e] > l1) { l1 = acc[e]; i1 = e; }
        float ex  = expf(l1 - l0);
        float w1v = ex / (1.f + ex);
        float w0v = 1.f - w1v;
        int p0 = atomicAdd(&g_cnt[i0], 1);
        int p1 = atomicAdd(&g_cnt[i1], 1);
        g_tok[i0 * NT + p0] = t;
        g_tok[i1 * NT + p1] = t;
        g_slot[2 * t]     = i0 * NT + p0;
        g_slot[2 * t + 1] = i1 * NT + p1;
        g_wt[2 * t]     = w0v;
        g_wt[2 * t + 1] = w1v;
        g_eid[2 * t]     = i0;
        g_eid[2 * t + 1] = i1;
    }
}

// ======================= cg2 GEMM1 + SwiGLU =======================
// Pair covers M=512 (2 tile-sets of 256; each CTA holds 128 rows/set), N=256 (128a+128g,
// B split: rank0 holds a-cols, rank1 g-cols). K=1024 in 16 chunks of 64; two k-half pipes.
__global__ __launch_bounds__(256, 1) __cluster_dims__(2, 1, 1)
void gemm1_tc(const float* __restrict__ x,
              const float* __restrict__ W1,
              const float* __restrict__ b1) {
#if TC_OK
    int e    = blockIdx.z;
    int cnt  = g_cnt[e];
    int row0 = (blockIdx.x >> 1) * 512;
    if (row0 >= cnt) return;           // pair-uniform exit
    int na0 = blockIdx.y * 128;
    uint32_t rank = ctarank();

    extern __shared__ char dynsmem[];
    uint32_t raw   = smem_u32(dynsmem);
    uint32_t base  = (raw + 1023) & ~1023u;
    uint32_t hdr   = base;
    uint32_t data0 = base + 1024;
    char* pdata = dynsmem + (data0 - raw);

    int tid = threadIdx.x, wid = tid >> 5, lane = tid & 31;
    int pp = wid >> 2;            // pipe = k-half
    int ptid = tid & 127;

    if (tid == 0) {
        MBAR_INIT(hdr + 8, 1);  MBAR_INIT(hdr + 16, 1);   // done (commit mc)
        MBAR_INIT(hdr + 24, 2); MBAR_INIT(hdr + 32, 2);   // ready (rank0, 2 arrivals)
    }
    if (wid == 0) { TCG_ALLOC2(hdr, 512); TCG_RELINQ2(); }
    __syncthreads();
    uint32_t tmem;
    asm("ld.shared.b32 %0, [%1];" : "=r"(tmem) : "r"(hdr));

    // zero D (our 512 cols) so all MMAs accumulate
    {
        uint32_t zb = tmem + ((uint32_t)(wid & 3) << 21) + (uint32_t)(pp * 256);
#pragma unroll
        for (int j = 0; j < 8; j++) TCG_ST32_Z(zb + j * 32);
        TCG_WAIT_ST();
    }
    TCG_FENCE_BEFORE();
    __syncthreads();
    CLUSTER_SYNC();               // barriers + zeroed D visible cluster-wide
    TCG_FENCE_AFTER();

    // A: thread owns row (row0 + s*256 + rank*128 + ptid) for sets s=0,1; k-half pp
    const float* ap[2];
#pragma unroll
    for (int s = 0; s < 2; s++) {
        int rr = row0 + s * 256 + (int)rank * 128 + ptid;
        if (rr >= cnt) rr = cnt - 1;
        ap[s] = x + (size_t)g_tok[e * NT + rr] * ND + pp * 32;
    }
    // B: thread owns one column of our 128-col half; k-half pp
    const float* bcol = W1 + (size_t)e * ND * N2F +
        ((rank == 0) ? (size_t)(na0 + ptid) : ((size_t)NF + na0 + ptid));

    uint64_t dA0 = descK(data0);
    uint64_t dB0 = descK(data0 + OFF_B);
    uint32_t mbD = hdr + 8 + 8 * pp;
    uint32_t mbR = hdr + 24 + 8 * pp;

    const int CH = ND / 64; // 16
    for (int c = 0; c < CH; c++) {
        int k0 = c * 64;
        float4 av[2][8];
#pragma unroll
        for (int s = 0; s < 2; s++) {
            const float4* p = (const float4*)(ap[s] + k0);
#pragma unroll
            for (int j = 0; j < 8; j++) av[s][j] = p[j];
        }
        float bv[32];
        {
            const float* gc = bcol + (size_t)(k0 + pp * 32) * N2F;
#pragma unroll
            for (int j = 0; j < 32; j++) bv[j] = gc[(size_t)j * N2F];
        }
        if (c >= 1) MBAR_WAIT_CL(mbD, (c - 1) & 1);
#pragma unroll
        for (int s = 0; s < 2; s++) {
            char* sa = pdata + s * 32768;
#pragma unroll
            for (int i = 0; i < 4; i++) {
                uint4 hi, lo; split8(av[s][2 * i], av[s][2 * i + 1], hi, lo);
                uint32_t off = SWZ((uint32_t)(ptid * 128 + pp * 64 + i * 16));
                *(uint4*)(sa + off)         = hi;
                *(uint4*)(sa + 16384 + off) = lo;
            }
        }
        {
            char* sb = pdata + OFF_B;
#pragma unroll
            for (int kb = 0; kb < 4; kb++) {
                float4 v0 = {bv[8*kb], bv[8*kb+1], bv[8*kb+2], bv[8*kb+3]};
                float4 v1 = {bv[8*kb+4], bv[8*kb+5], bv[8*kb+6], bv[8*kb+7]};
                uint4 hi, lo; split8(v0, v1, hi, lo);
                uint32_t off = SWZ((uint32_t)(ptid * 128 + pp * 64 + kb * 16));
                *(uint4*)(sb + off)         = hi;
                *(uint4*)(sb + 16384 + off) = lo;
            }
        }
        FENCE_ASYNC();
        BAR_SYNC(1 + pp, 128);
        if ((wid & 3) == 0 && elect1()) {
            MBAR_ARRIVE_R0(mbR);                  // release: our stores visible cluster-wide
            if (rank == 0) {
                MBAR_WAIT_CL(mbR, c & 1);          // acquire: both CTAs' stores visible
#pragma unroll
                for (int pi = 0; pi < 3; pi++) {
                    uint64_t aBase = dA0 + (uint64_t)((pi == 2) ? 1024 : 0);
                    uint64_t bBase = dB0 + (uint64_t)((pi == 1) ? 1024 : 0);
#pragma unroll
                    for (int ksl = 0; ksl < 2; ksl++) {
                        int ks = 2 * pp + ksl;
#pragma unroll
                        for (int s = 0; s < 2; s++) {
                            uint64_t ad = aBase + (uint64_t)(s * 2048 + ks * 2);
                            uint64_t bd = bBase + (uint64_t)(ks * 2);
                            mma2_n256(tmem + s * 256, ad, bd);
                        }
                    }
                }
                TCG_COMMIT_MC(mbD, 0x3);
            }
        }
    }
    __syncthreads();
    MBAR_WAIT_CL(hdr + 8,  (CH - 1) & 1);
    MBAR_WAIT_CL(hdr + 16, (CH - 1) & 1);
    TCG_FENCE_AFTER();
    int tl = wid >> 2;
    int row = row0 + tl * 256 + (int)rank * 128 + (wid & 3) * 32 + lane;
    bool act = row < cnt;
    const float* b1a = b1 + (size_t)e * N2F + na0;
    const float* b1g = b1 + (size_t)e * N2F + NF + na0;
    for (int j = 0; j < 4; j++) {
        uint32_t ar[32], gr[32];
        TCG_LD32(ar, tmem + tl * 256 + j * 32);
        TCG_LD32(gr, tmem + tl * 256 + 128 + j * 32);
        TCG_WAIT_LD();
        if (act) {
            uint32_t pk[32];
#pragma unroll
            for (int q = 0; q < 32; q++) {
                float avv = __uint_as_float(ar[q]) + b1a[j * 32 + q];
                float gvv = __uint_as_float(gr[q]) + b1g[j * 32 + q];
                float hv = avv * (gvv / (1.f + __expf(-gvv)));
                uint32_t u = __float_as_uint(hv);
                float lof = hv - __uint_as_float(u & 0xffff0000u);
                uint16_t lob = __bfloat16_as_ushort(__float2bfloat16(lof));
                pk[q] = (u >> 16) | ((uint32_t)lob << 16);
            }
            uint32_t* dst = g_hidden_pk + ((size_t)e * NT + row) * NF + na0 + j * 32;
#pragma unroll
            for (int q = 0; q < 8; q++) *(uint4*)(dst + 4 * q) = *(uint4*)&pk[4 * q];
        }
    }
    TCG_FENCE_BEFORE();
    __syncthreads();
    if (tid == 0) {
        MBAR_INVAL(hdr + 8);  MBAR_INVAL(hdr + 16);
        MBAR_INVAL(hdr + 24); MBAR_INVAL(hdr + 32);
    }
    CLUSTER_SYNC();
    if (wid == 0) { TCG_DEALLOC2(tmem, 512); }
#endif
}

// ======================= cg2 GEMM2 =======================
// Pair M=512, N=256 (rank r holds cols n0+r*128..+128), K=2048 in 32 chunks of 64.
__global__ __launch_bounds__(256, 1) __cluster_dims__(2, 1, 1)
void gemm2_tc(const float* __restrict__ W2) {
#if TC_OK
    int e    = blockIdx.z;
    int cnt  = g_cnt[e];
    int row0 = (blockIdx.x >> 1) * 512;
    if (row0 >= cnt) return;
    int n0 = blockIdx.y * 256;
    uint32_t rank = ctarank();

    extern __shared__ char dynsmem[];
    uint32_t raw   = smem_u32(dynsmem);
    uint32_t base  = (raw + 1023) & ~1023u;
    uint32_t hdr   = base;
    uint32_t data0 = base + 1024;
    char* pdata = dynsmem + (data0 - raw);

    int tid = threadIdx.x, wid = tid >> 5, lane = tid & 31;
    int pp = wid >> 2;
    int ptid = tid & 127;

    if (tid == 0) {
        MBAR_INIT(hdr + 8, 1);  MBAR_INIT(hdr + 16, 1);
        MBAR_INIT(hdr + 24, 2); MBAR_INIT(hdr + 32, 2);
    }
    if (wid == 0) { TCG_ALLOC2(hdr, 512); TCG_RELINQ2(); }
    __syncthreads();
    uint32_t tmem;
    asm("ld.shared.b32 %0, [%1];" : "=r"(tmem) : "r"(hdr));

    {
        uint32_t zb = tmem + ((uint32_t)(wid & 3) << 21) + (uint32_t)(pp * 256);
#pragma unroll
        for (int j = 0; j < 8; j++) TCG_ST32_Z(zb + j * 32);
        TCG_WAIT_ST();
    }
    TCG_FENCE_BEFORE();
    __syncthreads();
    CLUSTER_SYNC();
    TCG_FENCE_AFTER();

    const uint32_t* hp[2];
#pragma unroll
    for (int s = 0; s < 2; s++) {
        int rr = row0 + s * 256 + (int)rank * 128 + ptid;
        if (rr >= cnt) rr = cnt - 1;
        hp[s] = g_hidden_pk + ((size_t)e * NT + rr) * NF + pp * 32;
    }
    const float* bcol = W2 + (size_t)e * NF * ND + n0 + (int)rank * 128 + ptid;

    uint64_t dA0 = descK(data0);
    uint64_t dB0 = descK(data0 + OFF_B);
    uint32_t mbD = hdr + 8 + 8 * pp;
    uint32_t mbR = hdr + 24 + 8 * pp;

    const int CH = NF / 64; // 32
    for (int c = 0; c < CH; c++) {
        int k0 = c * 64;
        uint4 aw[2][8];
#pragma unroll
        for (int s = 0; s < 2; s++) {
            const uint4* p = (const uint4*)(hp[s] + k0);
#pragma unroll
            for (int j = 0; j < 8; j++) aw[s][j] = p[j];
        }
        float bv[32];
        {
            const float* gc = bcol + (size_t)(k0 + pp * 32) * ND;
#pragma unroll
            for (int j = 0; j < 32; j++) bv[j] = gc[(size_t)j * ND];
        }
        if (c >= 1) MBAR_WAIT_CL(mbD, (c - 1) & 1);
#pragma unroll
        for (int s = 0; s < 2; s++) {
            char* sa = pdata + s * 32768;
#pragma unroll
            for (int i = 0; i < 4; i++) {
                uint4 w0 = aw[s][2 * i], w1 = aw[s][2 * i + 1];
                uint4 hi, lo;
                hi.x = __byte_perm(w0.x, w0.y, 0x5410); lo.x = __byte_perm(w0.x, w0.y, 0x7632);
                hi.y = __byte_perm(w0.z, w0.w, 0x5410); lo.y = __byte_perm(w0.z, w0.w, 0x7632);
                hi.z = __byte_perm(w1.x, w1.y, 0x5410); lo.z = __byte_perm(w1.x, w1.y, 0x7632);
                hi.w = __byte_perm(w1.z, w1.w, 0x5410); lo.w = __byte_perm(w1.z, w1.w, 0x7632);
                uint32_t off = SWZ((uint32_t)(ptid * 128 + pp * 64 + i * 16));
                *(uint4*)(sa + off)         = hi;
                *(uint4*)(sa + 16384 + off) = lo;
            }
        }
        {
            char* sb = pdata + OFF_B;
#pragma unroll
            for (int kb = 0; kb < 4; kb++) {
                float4 v0 = {bv[8*kb], bv[8*kb+1], bv[8*kb+2], bv[8*kb+3]};
                float4 v1 = {bv[8*kb+4], bv[8*kb+5], bv[8*kb+6], bv[8*kb+7]};
                uint4 hi, lo; split8(v0, v1, hi, lo);
                uint32_t off = SWZ((uint32_t)(ptid * 128 + pp * 64 + kb * 16));
                *(uint4*)(sb + off)         = hi;
                *(uint4*)(sb + 16384 + off) = lo;
            }
        }
        FENCE_ASYNC();
        BAR_SYNC(1 + pp, 128);
        if ((wid & 3) == 0 && elect1()) {
            MBAR_ARRIVE_R0(mbR);
            if (rank == 0) {
                MBAR_WAIT_CL(mbR, c & 1);
#pragma unroll
                for (int pi = 0; pi < 3; pi++) {
                    uint64_t aBase = dA0 + (uint64_t)((pi == 2) ? 1024 : 0);
                    uint64_t bBase = dB0 + (uint64_t)((pi == 1) ? 1024 : 0);
#pragma unroll
                    for (int ksl = 0; ksl < 2; ksl++) {
                        int ks = 2 * pp + ksl;
#pragma unroll
                        for (int s = 0; s < 2; s++) {
                            uint64_t ad = aBase + (uint64_t)(s * 2048 + ks * 2);
                            uint64_t bd = bBase + (uint64_t)(ks * 2);
                            mma2_n256(tmem + s * 256, ad, bd);
                        }
                    }
                }
                TCG_COMMIT_MC(mbD, 0x3);
            }
        }
    }
    __syncthreads();
    MBAR_WAIT_CL(hdr + 8,  (CH - 1) & 1);
    MBAR_WAIT_CL(hdr + 16, (CH - 1) & 1);
    TCG_FENCE_AFTER();
    int tl = wid >> 2;
    int row = row0 + tl * 256 + (int)rank * 128 + (wid & 3) * 32 + lane;
    bool act = row < cnt;
    for (int j = 0; j < 8; j++) {
        uint32_t yr[32];
        TCG_LD32(yr, tmem + tl * 256 + j * 32);
        TCG_WAIT_LD();
        if (act) {
            float* dst = g_y + ((size_t)e * NT + row) * ND + n0 + j * 32;
#pragma unroll
            for (int q = 0; q < 8; q++) *(uint4*)(dst + 4 * q) = *(uint4*)&yr[4 * q];
        }
    }
    TCG_FENCE_BEFORE();
    __syncthreads();
    if (tid == 0) {
        MBAR_INVAL(hdr + 8);  MBAR_INVAL(hdr + 16);
        MBAR_INVAL(hdr + 24); MBAR_INVAL(hdr + 32);
    }
    CLUSTER_SYNC();
    if (wid == 0) { TCG_DEALLOC2(tmem, 512); }
#endif
}

// ======================= combine =======================
__global__ void combine_kernel(const float* __restrict__ b2, float* __restrict__ out) {
    int t = blockIdx.x;
    float w0 = g_wt[2 * t], w1 = g_wt[2 * t + 1];
    int s0 = g_slot[2 * t], s1 = g_slot[2 * t + 1];
    int e0 = g_eid[2 * t],  e1 = g_eid[2 * t + 1];
    int c = threadIdx.x * 4;
    float4 y0  = *(const float4*)(g_y + (size_t)s0 * ND + c);
    float4 y1  = *(const float4*)(g_y + (size_t)s1 * ND + c);
    float4 bb0 = *(const float4*)(b2 + (size_t)e0 * ND + c);
    float4 bb1 = *(const float4*)(b2 + (size_t)e1 * ND + c);
    float4 o;
    o.x = w0 * (y0.x + bb0.x) + w1 * (y1.x + bb1.x);
    o.y = w0 * (y0.y + bb0.y) + w1 * (y1.y + bb1.y);
    o.z = w0 * (y0.z + bb0.z) + w1 * (y1.z + bb1.z);
    o.w = w0 * (y0.w + bb0.w) + w1 * (y1.w + bb1.w);
    *(float4*)(out + (size_t)t * ND + c) = o;
}

// ======================= launch =======================
extern "C" void kernel_launch(void* const* d_in, const int* in_sizes, int n_in,
                              void* d_out, int out_size) {
    const float* x    = (const float*)d_in[0];
    const float* Wr   = (const float*)d_in[1];
    const float* temp = (const float*)d_in[2];
    const float* W1   = (const float*)d_in[3];
    const float* b1   = (const float*)d_in[4];
    const float* W2   = (const float*)d_in[5];
    const float* b2   = (const float*)d_in[6];
    float* out = (float*)d_out;

    cudaFuncSetAttribute(gemm1_tc, cudaFuncAttributeMaxDynamicSharedMemorySize, DYNSMEM);
    cudaFuncSetAttribute(gemm2_tc, cudaFuncAttributeMaxDynamicSharedMemorySize, DYNSMEM);

    zero_cnt_kernel<<<1, 32>>>();
    router_kernel<<<NT / 8, 256>>>(x, Wr, temp);
    gemm1_tc<<<dim3((NT / 512) * 2, NF / 128, NE), 256, DYNSMEM>>>(x, W1, b1);
    gemm2_tc<<<dim3((NT / 512) * 2, ND / 256, NE), 256, DYNSMEM>>>(W2);
    combine_kernel<<<NT, 256>>>(b2, out);
}

// round 17
// speedup vs baseline: 1.1425x; 1.0190x over previous
#include <cuda_runtime.h>
#include <cuda_bf16.h>
#include <cstdint>
#include <math.h>

#define NT 4096
#define ND 1024
#define NE 8
#define NF 2048
#define N2F 4096

#if defined(__CUDA_ARCH_FEAT_SM103_ALL) || defined(__CUDA_ARCH_FEAT_SM100_ALL)
#define TC_OK 1
#else
#define TC_OK 0
#endif

// ---------------- scratch ----------------
__device__ int      g_cnt[NE];
__device__ int      g_tok[NE * NT];
__device__ float    g_wt[NT * 2];
__device__ int      g_slot[NT * 2];
__device__ int      g_eid[NT * 2];
__device__ uint32_t g_hidden_pk[(size_t)NE * NT * NF]; // bf16 hi|lo pack
__device__ float    g_y[(size_t)NE * NT * ND];

// ---------------- helpers ----------------
__device__ __forceinline__ uint32_t smem_u32(const void* p) {
    uint32_t a;
    asm("{ .reg .u64 t; cvta.to.shared.u64 t, %1; cvt.u32.u64 %0, t; }" : "=r"(a) : "l"(p));
    return a;
}
__device__ __forceinline__ uint32_t elect1() {
    uint32_t r;
    asm volatile("{ .reg .pred p; elect.sync _|p, 0xFFFFFFFF; selp.b32 %0,1,0,p; }" : "=r"(r));
    return r;
}
__device__ __forceinline__ uint32_t ctarank() {
    uint32_t r; asm("mov.u32 %0, %%cluster_ctarank;" : "=r"(r)); return r;
}
#define MBAR_INIT(a, c) asm volatile("mbarrier.init.shared.b64 [%0], %1;" :: "r"(a), "r"(c) : "memory")
#define MBAR_INVAL(a)   asm volatile("mbarrier.inval.shared.b64 [%0];" :: "r"(a) : "memory")
#define MBAR_WAIT_CL(a, ph) do { uint32_t _m=(a); uint32_t _p=(ph); uint32_t _d;                            \
    asm volatile("{ .reg .pred p; mbarrier.try_wait.parity.acquire.cluster.shared::cta.b64 p,[%1],%2; "    \
                 "selp.b32 %0,1,0,p; }" : "=r"(_d) : "r"(_m), "r"(_p) : "memory");                          \
    if (!_d) { asm volatile("{ .reg .pred P1; WL%=: "                                                      \
        "mbarrier.try_wait.parity.acquire.cluster.shared::cta.b64 P1,[%0],%1,0x989680; "                   \
        "@P1 bra.uni WD%=; bra.uni WL%=; WD%=: }" :: "r"(_m), "r"(_p) : "memory"); } } while (0)
// cta-scope async-proxy fence (R15-verified). Cross-CTA ordering comes from the
// release-arrive + acquire-wait pair on rank0's mbarrier.
#define FENCE_ASYNC() asm volatile("fence.proxy.async.shared::cta;" ::: "memory")
#define BAR_SYNC(id, n) asm volatile("bar.sync %0, %1;" :: "r"(id), "r"(n) : "memory")
#define CLUSTER_SYNC() do { \
    asm volatile("barrier.cluster.arrive.aligned;" ::: "memory"); \
    asm volatile("barrier.cluster.wait.aligned;" ::: "memory"); } while (0)
#define MBAR_ARRIVE_R0(local_a) do { uint32_t _r;                                        \
    asm("mapa.shared::cluster.u32 %0, %1, 0;" : "=r"(_r) : "r"(local_a));                \
    asm volatile("mbarrier.arrive.shared::cluster.b64 _, [%0];" :: "r"(_r) : "memory"); } while (0)

#define SWZ(x) ((x) ^ (((x) >> 3) & 0x70))

#if TC_OK
#define TCG_ALLOC2(sa, n)  asm volatile("tcgen05.alloc.cta_group::2.sync.aligned.shared::cta.b32 [%0], %1;" :: "r"(sa), "r"(n) : "memory")
#define TCG_DEALLOC2(t, n) asm volatile("tcgen05.dealloc.cta_group::2.sync.aligned.b32 %0, %1;" :: "r"(t), "r"(n))
#define TCG_RELINQ2()      asm volatile("tcgen05.relinquish_alloc_permit.cta_group::2.sync.aligned;")
#define TCG_COMMIT_MC(a, m) asm volatile( \
    "tcgen05.commit.cta_group::2.mbarrier::arrive::one.shared::cluster.multicast::cluster.b64 [%0], %1;" \
    :: "r"(a), "h"((uint16_t)(m)) : "memory")
#define TCG_FENCE_AFTER()  asm volatile("tcgen05.fence::after_thread_sync;" ::: "memory")
#define TCG_FENCE_BEFORE() asm volatile("tcgen05.fence::before_thread_sync;" ::: "memory")
#define TCG_WAIT_LD()      asm volatile("tcgen05.wait::ld.sync.aligned;" ::: "memory")
#define TCG_WAIT_ST()      asm volatile("tcgen05.wait::st.sync.aligned;" ::: "memory")

#define TCG_LD32(r, ta) \
    asm volatile("tcgen05.ld.sync.aligned.32x32b.x32.b32 " \
        "{%0,%1,%2,%3,%4,%5,%6,%7,%8,%9,%10,%11,%12,%13,%14,%15," \
        "%16,%17,%18,%19,%20,%21,%22,%23,%24,%25,%26,%27,%28,%29,%30,%31}, [%32];" \
        : "=r"((r)[0]),"=r"((r)[1]),"=r"((r)[2]),"=r"((r)[3]),"=r"((r)[4]),"=r"((r)[5]),"=r"((r)[6]),"=r"((r)[7]), \
          "=r"((r)[8]),"=r"((r)[9]),"=r"((r)[10]),"=r"((r)[11]),"=r"((r)[12]),"=r"((r)[13]),"=r"((r)[14]),"=r"((r)[15]), \
          "=r"((r)[16]),"=r"((r)[17]),"=r"((r)[18]),"=r"((r)[19]),"=r"((r)[20]),"=r"((r)[21]),"=r"((r)[22]),"=r"((r)[23]), \
          "=r"((r)[24]),"=r"((r)[25]),"=r"((r)[26]),"=r"((r)[27]),"=r"((r)[28]),"=r"((r)[29]),"=r"((r)[30]),"=r"((r)[31]) \
        : "r"(ta))

#define TCG_ST32_Z(ta) \
    asm volatile("tcgen05.st.sync.aligned.32x32b.x32.b32 [%0], " \
        "{%1,%1,%1,%1,%1,%1,%1,%1,%1,%1,%1,%1,%1,%1,%1,%1," \
        "%1,%1,%1,%1,%1,%1,%1,%1,%1,%1,%1,%1,%1,%1,%1,%1};" \
        :: "r"(ta), "r"(0u) : "memory")

__device__ __forceinline__ uint64_t descK(uint32_t a) {   // K-major SW128: LBO=1, SBO=64
    return ((uint64_t)2 << 61) | ((uint64_t)1 << 46) | ((uint64_t)64 << 32) |
           ((uint64_t)1 << 16) | ((a >> 4) & 0x3FFF);
}
// cg2 kind::f16 idesc: dtype=F32, a/btype=BF16, K-major, N=256, M=256
#define IDESC2 ((1u<<4) | (1u<<7) | (1u<<10) | (32u<<17) | (16u<<24))

__device__ __forceinline__ void mma2_n256(uint32_t d, uint64_t ad, uint64_t bd) {
    asm volatile("{ .reg .pred p; setp.ne.u32 p, %4, 0;\n\t"
        "tcgen05.mma.cta_group::2.kind::f16 [%0], %1, %2, %3, {%5,%5,%5,%5,%5,%5,%5,%5}, p; }"
        :: "r"(d), "l"(ad), "l"(bd), "r"(IDESC2), "r"(1u), "r"(0u) : "memory");
}
#endif // TC_OK

__device__ __forceinline__ uint32_t bf2(float h, float l) {
    uint32_t r; asm("cvt.rn.bf16x2.f32 %0, %1, %2;" : "=r"(r) : "f"(h), "f"(l)); return r;
}
__device__ __forceinline__ void split8(float4 v0, float4 v1, uint4& hi, uint4& lo) {
    uint32_t u0 = __float_as_uint(v0.x), u1 = __float_as_uint(v0.y);
    uint32_t u2 = __float_as_uint(v0.z), u3 = __float_as_uint(v0.w);
    uint32_t u4 = __float_as_uint(v1.x), u5 = __float_as_uint(v1.y);
    uint32_t u6 = __float_as_uint(v1.z), u7 = __float_as_uint(v1.w);
    hi.x = __byte_perm(u0, u1, 0x7632); hi.y = __byte_perm(u2, u3, 0x7632);
    hi.z = __byte_perm(u4, u5, 0x7632); hi.w = __byte_perm(u6, u7, 0x7632);
    float l0 = v0.x - __uint_as_float(u0 & 0xffff0000u);
    float l1 = v0.y - __uint_as_float(u1 & 0xffff0000u);
    float l2 = v0.z - __uint_as_float(u2 & 0xffff0000u);
    float l3 = v0.w - __uint_as_float(u3 & 0xffff0000u);
    float l4 = v1.x - __uint_as_float(u4 & 0xffff0000u);
    float l5 = v1.y - __uint_as_float(u5 & 0xffff0000u);
    float l6 = v1.z - __uint_as_float(u6 & 0xffff0000u);
    float l7 = v1.w - __uint_as_float(u7 & 0xffff0000u);
    lo.x = bf2(l1, l0); lo.y = bf2(l3, l2); lo.z = bf2(l5, l4); lo.w = bf2(l7, l6);
}

// SMEM per CTA (after 1024-aligned data0):
//   A: set s (0,1) @ s*32768; plane hi @+0, lo @+16384   (64 KB: CTA's 128 rows per set)
//   B: hi @ 65536, lo @ 81920                            (32 KB: CTA's 128-col half)
// hdr: done[pp] @ 8+pp*8 (pp=0..3, commit mc); ready[pp] @ 40+pp*8 (count 2, rank0)
#define OFF_B    65536
#define DYNSMEM  100352

// ======================= zero counters =======================
__global__ void zero_cnt_kernel() {
    if (threadIdx.x < NE) g_cnt[threadIdx.x] = 0;
}

// ======================= router =======================
__global__ void router_kernel(const float* __restrict__ x,
                              const float* __restrict__ Wr,
                              const float* __restrict__ temp) {
    int t    = (blockIdx.x * blockDim.x + threadIdx.x) >> 5;
    int lane = threadIdx.x & 31;
    if (t >= NT) return;
    const float4* xr = (const float4*)(x + (size_t)t * ND);
    const float4* wr4 = (const float4*)Wr;
    float acc[NE];
#pragma unroll
    for (int e = 0; e < NE; e++) acc[e] = 0.f;
    for (int d4 = lane; d4 < ND / 4; d4 += 32) {
        float4 xv = xr[d4];
        float xs[4] = {xv.x, xv.y, xv.z, xv.w};
#pragma unroll
        for (int j = 0; j < 4; j++) {
            int d = 4 * d4 + j;
            float4 w0 = wr4[d * 2], w1 = wr4[d * 2 + 1];
            acc[0] = fmaf(xs[j], w0.x, acc[0]);
            acc[1] = fmaf(xs[j], w0.y, acc[1]);
            acc[2] = fmaf(xs[j], w0.z, acc[2]);
            acc[3] = fmaf(xs[j], w0.w, acc[3]);
            acc[4] = fmaf(xs[j], w1.x, acc[4]);
            acc[5] = fmaf(xs[j], w1.y, acc[5]);
            acc[6] = fmaf(xs[j], w1.z, acc[6]);
            acc[7] = fmaf(xs[j], w1.w, acc[7]);
        }
    }
#pragma unroll
    for (int e = 0; e < NE; e++) {
#pragma unroll
        for (int off = 16; off > 0; off >>= 1)
            acc[e] += __shfl_xor_sync(0xffffffffu, acc[e], off);
    }
    if (lane == 0) {
        float ti = 1.0f / temp[0];
#pragma unroll
        for (int e = 0; e < NE; e++) acc[e] *= ti;
        int i0 = 0; float l0 = acc[0];
#pragma unroll
        for (int e = 1; e < NE; e++) if (acc[e] > l0) { l0 = acc[e]; i0 = e; }
        int i1 = -1; float l1 = -3.4e38f;
#pragma unroll
        for (int e = 0; e < NE; e++)
            if (e != i0 && acc[e] > l1) { l1 = acc[e]; i1 = e; }
        float ex  = expf(l1 - l0);
        float w1v = ex / (1.f + ex);
        float w0v = 1.f - w1v;
        int p0 = atomicAdd(&g_cnt[i0], 1);
        int p1 = atomicAdd(&g_cnt[i1], 1);
        g_tok[i0 * NT + p0] = t;
        g_tok[i1 * NT + p1] = t;
        g_slot[2 * t]     = i0 * NT + p0;
        g_slot[2 * t + 1] = i1 * NT + p1;
        g_wt[2 * t]     = w0v;
        g_wt[2 * t + 1] = w1v;
        g_eid[2 * t]     = i0;
        g_eid[2 * t + 1] = i1;
    }
}

// ======================= cg2 GEMM1 + SwiGLU (4 k-pipes) =======================
__global__ __launch_bounds__(256, 1) __cluster_dims__(2, 1, 1)
void gemm1_tc(const float* __restrict__ x,
              const float* __restrict__ W1,
              const float* __restrict__ b1) {
#if TC_OK
    int e    = blockIdx.z;
    int cnt  = g_cnt[e];
    int row0 = (blockIdx.x >> 1) * 512;
    if (row0 >= cnt) return;
    int na0 = blockIdx.y * 128;
    uint32_t rank = ctarank();

    extern __shared__ char dynsmem[];
    uint32_t raw   = smem_u32(dynsmem);
    uint32_t base  = (raw + 1023) & ~1023u;
    uint32_t hdr   = base;
    uint32_t data0 = base + 1024;
    char* pdata = dynsmem + (data0 - raw);

    int tid = threadIdx.x, wid = tid >> 5, lane = tid & 31;
    int pp = wid >> 1;            // pipe = k-slice (0..3)
    int ptid = tid & 63;

    if (tid == 0) {
#pragma unroll
        for (int p2 = 0; p2 < 4; p2++) {
            MBAR_INIT(hdr + 8 + 8 * p2, 1);
            MBAR_INIT(hdr + 40 + 8 * p2, 2);
        }
    }
    if (wid == 0) { TCG_ALLOC2(hdr, 512); TCG_RELINQ2(); }
    __syncthreads();
    uint32_t tmem;
    asm("ld.shared.b32 %0, [%1];" : "=r"(tmem) : "r"(hdr));

    {
        uint32_t zb = tmem + ((uint32_t)(wid & 3) << 21) + (uint32_t)((wid >> 2) * 256);
#pragma unroll
        for (int j = 0; j < 8; j++) TCG_ST32_Z(zb + j * 32);
        TCG_WAIT_ST();
    }
    TCG_FENCE_BEFORE();
    __syncthreads();
    CLUSTER_SYNC();
    TCG_FENCE_AFTER();

    const float* ap[2][2];
#pragma unroll
    for (int s = 0; s < 2; s++)
#pragma unroll
        for (int h = 0; h < 2; h++) {
            int rr = row0 + s * 256 + (int)rank * 128 + ptid + h * 64;
            if (rr >= cnt) rr = cnt - 1;
            ap[s][h] = x + (size_t)g_tok[e * NT + rr] * ND + pp * 16;
        }
    const float* bcol[2];
#pragma unroll
    for (int h = 0; h < 2; h++) {
        int col = ptid + h * 64;
        bcol[h] = W1 + (size_t)e * ND * N2F +
            ((rank == 0) ? (size_t)(na0 + col) : ((size_t)NF + na0 + col));
    }

    uint64_t dA0 = descK(data0);
    uint64_t dB0 = descK(data0 + OFF_B);
    uint32_t mbD = hdr + 8 + 8 * pp;
    uint32_t mbR = hdr + 40 + 8 * pp;

    const int CH = ND / 64; // 16
    for (int c = 0; c < CH; c++) {
        int k0 = c * 64;
        float4 av[2][2][4];
#pragma unroll
        for (int s = 0; s < 2; s++)
#pragma unroll
            for (int h = 0; h < 2; h++) {
                const float4* p = (const float4*)(ap[s][h] + k0);
#pragma unroll
                for (int j = 0; j < 4; j++) av[s][h][j] = p[j];
            }
        float bv[2][16];
#pragma unroll
        for (int h = 0; h < 2; h++) {
            const float* gc = bcol[h] + (size_t)(k0 + pp * 16) * N2F;
#pragma unroll
            for (int j = 0; j < 16; j++) bv[h][j] = gc[(size_t)j * N2F];
        }
        if (c >= 1) MBAR_WAIT_CL(mbD, (c - 1) & 1);
#pragma unroll
        for (int s = 0; s < 2; s++) {
            char* sa = pdata + s * 32768;
#pragma unroll
            for (int h = 0; h < 2; h++) {
                int r = ptid + h * 64;
#pragma unroll
                for (int i = 0; i < 2; i++) {
                    uint4 hi, lo; split8(av[s][h][2 * i], av[s][h][2 * i + 1], hi, lo);
                    uint32_t off = SWZ((uint32_t)(r * 128 + pp * 32 + i * 16));
                    *(uint4*)(sa + off)         = hi;
                    *(uint4*)(sa + 16384 + off) = lo;
                }
            }
        }
        {
            char* sb = pdata + OFF_B;
#pragma unroll
            for (int h = 0; h < 2; h++) {
                int n = ptid + h * 64;
#pragma unroll
                for (int i = 0; i < 2; i++) {
                    float4 v0 = {bv[h][8*i], bv[h][8*i+1], bv[h][8*i+2], bv[h][8*i+3]};
                    float4 v1 = {bv[h][8*i+4], bv[h][8*i+5], bv[h][8*i+6], bv[h][8*i+7]};
                    uint4 hi, lo; split8(v0, v1, hi, lo);
                    uint32_t off = SWZ((uint32_t)(n * 128 + pp * 32 + i * 16));
                    *(uint4*)(sb + off)         = hi;
                    *(uint4*)(sb + 16384 + off) = lo;
                }
            }
        }
        FENCE_ASYNC();
        BAR_SYNC(1 + pp, 64);
        if ((wid & 1) == 0 && elect1()) {
            MBAR_ARRIVE_R0(mbR);
            if (rank == 0) {
                MBAR_WAIT_CL(mbR, c & 1);
#pragma unroll
                for (int pi = 0; pi < 3; pi++) {
                    uint64_t aBase = dA0 + (uint64_t)((pi == 2) ? 1024 : 0);
                    uint64_t bBase = dB0 + (uint64_t)((pi == 1) ? 1024 : 0);
#pragma unroll
                    for (int s = 0; s < 2; s++) {
                        uint64_t ad = aBase + (uint64_t)(s * 2048 + pp * 2);
                        uint64_t bd = bBase + (uint64_t)(pp * 2);
                        mma2_n256(tmem + s * 256, ad, bd);
                    }
                }
                TCG_COMMIT_MC(mbD, 0x3);
            }
        }
    }
    __syncthreads();
#pragma unroll
    for (int p2 = 0; p2 < 4; p2++) MBAR_WAIT_CL(hdr + 8 + 8 * p2, (CH - 1) & 1);
    TCG_FENCE_AFTER();
    int tl = wid >> 2;
    int row = row0 + tl * 256 + (int)rank * 128 + (wid & 3) * 32 + lane;
    bool act = row < cnt;
    const float* b1a = b1 + (size_t)e * N2F + na0;
    const float* b1g = b1 + (size_t)e * N2F + NF + na0;
    for (int j = 0; j < 4; j++) {
        uint32_t ar[32], gr[32];
        TCG_LD32(ar, tmem + tl * 256 + j * 32);
        TCG_LD32(gr, tmem + tl * 256 + 128 + j * 32);
        TCG_WAIT_LD();
        if (act) {
            uint32_t pk[32];
#pragma unroll
            for (int q = 0; q < 32; q++) {
                float avv = __uint_as_float(ar[q]) + b1a[j * 32 + q];
                float gvv = __uint_as_float(gr[q]) + b1g[j * 32 + q];
                float hv = avv * (gvv / (1.f + __expf(-gvv)));
                uint32_t u = __float_as_uint(hv);
                float lof = hv - __uint_as_float(u & 0xffff0000u);
                uint16_t lob = __bfloat16_as_ushort(__float2bfloat16(lof));
                pk[q] = (u >> 16) | ((uint32_t)lob << 16);
            }
            uint32_t* dst = g_hidden_pk + ((size_t)e * NT + row) * NF + na0 + j * 32;
#pragma unroll
            for (int q = 0; q < 8; q++) *(uint4*)(dst + 4 * q) = *(uint4*)&pk[4 * q];
        }
    }
    TCG_FENCE_BEFORE();
    __syncthreads();
    if (tid == 0) {
#pragma unroll
        for (int p2 = 0; p2 < 4; p2++) { MBAR_INVAL(hdr + 8 + 8 * p2); MBAR_INVAL(hdr + 40 + 8 * p2); }
    }
    CLUSTER_SYNC();
    if (wid == 0) { TCG_DEALLOC2(tmem, 512); }
#endif
}

// ======================= cg2 GEMM2 (4 k-pipes; FIXED A slice width) =======================
__global__ __launch_bounds__(256, 1) __cluster_dims__(2, 1, 1)
void gemm2_tc(const float* __restrict__ W2) {
#if TC_OK
    int e    = blockIdx.z;
    int cnt  = g_cnt[e];
    int row0 = (blockIdx.x >> 1) * 512;
    if (row0 >= cnt) return;
    int n0 = blockIdx.y * 256;
    uint32_t rank = ctarank();

    extern __shared__ char dynsmem[];
    uint32_t raw   = smem_u32(dynsmem);
    uint32_t base  = (raw + 1023) & ~1023u;
    uint32_t hdr   = base;
    uint32_t data0 = base + 1024;
    char* pdata = dynsmem + (data0 - raw);

    int tid = threadIdx.x, wid = tid >> 5, lane = tid & 31;
    int pp = wid >> 1;
    int ptid = tid & 63;

    if (tid == 0) {
#pragma unroll
        for (int p2 = 0; p2 < 4; p2++) {
            MBAR_INIT(hdr + 8 + 8 * p2, 1);
            MBAR_INIT(hdr + 40 + 8 * p2, 2);
        }
    }
    if (wid == 0) { TCG_ALLOC2(hdr, 512); TCG_RELINQ2(); }
    __syncthreads();
    uint32_t tmem;
    asm("ld.shared.b32 %0, [%1];" : "=r"(tmem) : "r"(hdr));

    {
        uint32_t zb = tmem + ((uint32_t)(wid & 3) << 21) + (uint32_t)((wid >> 2) * 256);
#pragma unroll
        for (int j = 0; j < 8; j++) TCG_ST32_Z(zb + j * 32);
        TCG_WAIT_ST();
    }
    TCG_FENCE_BEFORE();
    __syncthreads();
    CLUSTER_SYNC();
    TCG_FENCE_AFTER();

    const uint32_t* hp[2][2];
#pragma unroll
    for (int s = 0; s < 2; s++)
#pragma unroll
        for (int h = 0; h < 2; h++) {
            int rr = row0 + s * 256 + (int)rank * 128 + ptid + h * 64;
            if (rr >= cnt) rr = cnt - 1;
            hp[s][h] = g_hidden_pk + ((size_t)e * NT + rr) * NF + pp * 16;
        }
    const float* bcol[2];
#pragma unroll
    for (int h = 0; h < 2; h++)
        bcol[h] = W2 + (size_t)e * NF * ND + n0 + (int)rank * 128 + ptid + h * 64;

    uint64_t dA0 = descK(data0);
    uint64_t dB0 = descK(data0 + OFF_B);
    uint32_t mbD = hdr + 8 + 8 * pp;
    uint32_t mbR = hdr + 40 + 8 * pp;

    const int CH = NF / 64; // 32
    for (int c = 0; c < CH; c++) {
        int k0 = c * 64;
        // A prefetch: FULL K=16 slice = 4 uint4 (16 packed words) per (set,row)
        uint4 aw[2][2][4];
#pragma unroll
        for (int s = 0; s < 2; s++)
#pragma unroll
            for (int h = 0; h < 2; h++) {
                const uint4* p = (const uint4*)(hp[s][h] + k0);
#pragma unroll
                for (int j = 0; j < 4; j++) aw[s][h][j] = p[j];
            }
        float bv[2][16];
#pragma unroll
        for (int h = 0; h < 2; h++) {
            const float* gc = bcol[h] + (size_t)(k0 + pp * 16) * ND;
#pragma unroll
            for (int j = 0; j < 16; j++) bv[h][j] = gc[(size_t)j * ND];
        }
        if (c >= 1) MBAR_WAIT_CL(mbD, (c - 1) & 1);
        // A unpack+store: 8 packed words -> 16B hi + 16B lo per i (i<2 covers 16 k-elems)
#pragma unroll
        for (int s = 0; s < 2; s++) {
            char* sa = pdata + s * 32768;
#pragma unroll
            for (int h = 0; h < 2; h++) {
                int r = ptid + h * 64;
#pragma unroll
                for (int i = 0; i < 2; i++) {
                    uint4 w0 = aw[s][h][2 * i], w1 = aw[s][h][2 * i + 1];
                    uint4 hi, lo;
                    hi.x = __byte_perm(w0.x, w0.y, 0x5410); lo.x = __byte_perm(w0.x, w0.y, 0x7632);
                    hi.y = __byte_perm(w0.z, w0.w, 0x5410); lo.y = __byte_perm(w0.z, w0.w, 0x7632);
                    hi.z = __byte_perm(w1.x, w1.y, 0x5410); lo.z = __byte_perm(w1.x, w1.y, 0x7632);
                    hi.w = __byte_perm(w1.z, w1.w, 0x5410); lo.w = __byte_perm(w1.z, w1.w, 0x7632);
                    uint32_t off = SWZ((uint32_t)(r * 128 + pp * 32 + i * 16));
                    *(uint4*)(sa + off)         = hi;
                    *(uint4*)(sa + 16384 + off) = lo;
                }
            }
        }
        {
            char* sb = pdata + OFF_B;
#pragma unroll
            for (int h = 0; h < 2; h++) {
                int n = ptid + h * 64;
#pragma unroll
                for (int i = 0; i < 2; i++) {
                    float4 v0 = {bv[h][8*i], bv[h][8*i+1], bv[h][8*i+2], bv[h][8*i+3]};
                    float4 v1 = {bv[h][8*i+4], bv[h][8*i+5], bv[h][8*i+6], bv[h][8*i+7]};
                    uint4 hi, lo; split8(v0, v1, hi, lo);
                    uint32_t off = SWZ((uint32_t)(n * 128 + pp * 32 + i * 16));
                    *(uint4*)(sb + off)         = hi;
                    *(uint4*)(sb + 16384 + off) = lo;
                }
            }
        }
        FENCE_ASYNC();
        BAR_SYNC(1 + pp, 64);
        if ((wid & 1) == 0 && elect1()) {
            MBAR_ARRIVE_R0(mbR);
            if (rank == 0) {
                MBAR_WAIT_CL(mbR, c & 1);
#pragma unroll
                for (int pi = 0; pi < 3; pi++) {
                    uint64_t aBase = dA0 + (uint64_t)((pi == 2) ? 1024 : 0);
                    uint64_t bBase = dB0 + (uint64_t)((pi == 1) ? 1024 : 0);
#pragma unroll
                    for (int s = 0; s < 2; s++) {
                        uint64_t ad = aBase + (uint64_t)(s * 2048 + pp * 2);
                        uint64_t bd = bBase + (uint64_t)(pp * 2);
                        mma2_n256(tmem + s * 256, ad, bd);
                    }
                }
                TCG_COMMIT_MC(mbD, 0x3);
            }
        }
    }
    __syncthreads();
#pragma unroll
    for (int p2 = 0; p2 < 4; p2++) MBAR_WAIT_CL(hdr + 8 + 8 * p2, (CH - 1) & 1);
    TCG_FENCE_AFTER();
    int tl = wid >> 2;
    int row = row0 + tl * 256 + (int)rank * 128 + (wid & 3) * 32 + lane;
    bool act = row < cnt;
    for (int j = 0; j < 8; j++) {
        uint32_t yr[32];
        TCG_LD32(yr, tmem + tl * 256 + j * 32);
        TCG_WAIT_LD();
        if (act) {
            float* dst = g_y + ((size_t)e * NT + row) * ND + n0 + j * 32;
#pragma unroll
            for (int q = 0; q < 8; q++) *(uint4*)(dst + 4 * q) = *(uint4*)&yr[4 * q];
        }
    }
    TCG_FENCE_BEFORE();
    __syncthreads();
    if (tid == 0) {
#pragma unroll
        for (int p2 = 0; p2 < 4; p2++) { MBAR_INVAL(hdr + 8 + 8 * p2); MBAR_INVAL(hdr + 40 + 8 * p2); }
    }
    CLUSTER_SYNC();
    if (wid == 0) { TCG_DEALLOC2(tmem, 512); }
#endif
}

// ======================= combine =======================
__global__ void combine_kernel(const float* __restrict__ b2, float* __restrict__ out) {
    int t = blockIdx.x;
    float w0 = g_wt[2 * t], w1 = g_wt[2 * t + 1];
    int s0 = g_slot[2 * t], s1 = g_slot[2 * t + 1];
    int e0 = g_eid[2 * t],  e1 = g_eid[2 * t + 1];
    int c = threadIdx.x * 4;
    float4 y0  = *(const float4*)(g_y + (size_t)s0 * ND + c);
    float4 y1  = *(const float4*)(g_y + (size_t)s1 * ND + c);
    float4 bb0 = *(const float4*)(b2 + (size_t)e0 * ND + c);
    float4 bb1 = *(const float4*)(b2 + (size_t)e1 * ND + c);
    float4 o;
    o.x = w0 * (y0.x + bb0.x) + w1 * (y1.x + bb1.x);
    o.y = w0 * (y0.y + bb0.y) + w1 * (y1.y + bb1.y);
    o.z = w0 * (y0.z + bb0.z) + w1 * (y1.z + bb1.z);
    o.w = w0 * (y0.w + bb0.w) + w1 * (y1.w + bb1.w);
    *(float4*)(out + (size_t)t * ND + c) = o;
}

// ======================= launch =======================
extern "C" void kernel_launch(void* const* d_in, const int* in_sizes, int n_in,
                              void* d_out, int out_size) {
    const float* x    = (const float*)d_in[0];
    const float* Wr   = (const float*)d_in[1];
    const float* temp = (const float*)d_in[2];
    const float* W1   = (const float*)d_in[3];
    const float* b1   = (const float*)d_in[4];
    const float* W2   = (const float*)d_in[5];
    const float* b2   = (const float*)d_in[6];
    float* out = (float*)d_out;

    cudaFuncSetAttribute(gemm1_tc, cudaFuncAttributeMaxDynamicSharedMemorySize, DYNSMEM);
    cudaFuncSetAttribute(gemm2_tc, cudaFuncAttributeMaxDynamicSharedMemorySize, DYNSMEM);

    zero_cnt_kernel<<<1, 32>>>();
    router_kernel<<<NT / 8, 256>>>(x, Wr, temp);
    gemm1_tc<<<dim3((NT / 512) * 2, NF / 128, NE), 256, DYNSMEM>>>(x, W1, b1);
    gemm2_tc<<<dim3((NT / 512) * 2, ND / 256, NE), 256, DYNSMEM>>>(W2);
    combine_kernel<<<NT, 256>>>(b2, out);
}